// round 5
// baseline (speedup 1.0000x reference)
#include <cuda_runtime.h>
#include <math.h>

#define NNODES 65535
#define IN_DIM 300
#define MEM 256
#define IOU 768          // 3*MEM
#define XCOLS 1024       // 768 iou + 256 fx
#define GCOLS 1280       // 768 iou-rec + 256 f_l + 256 f_r
#define NINTERNAL 32767
#define LEAF_START 32767
#define NLEAF 32768

typedef unsigned long long u64;

// Scratch (allocation-free rule: __device__ globals)
__device__ float g_P[(size_t)NNODES * XCOLS];   // x-projections (+folded biases)
__device__ float g_G[(size_t)16384 * GCOLS];    // per-level recurrent GEMM out
__device__ float g_bias[XCOLS];

__device__ __forceinline__ float sigmoidf_(float x) { return 1.0f / (1.0f + __expf(-x)); }
__device__ __forceinline__ float tanhf_(float x)    { return 1.0f - 2.0f / (__expf(2.0f * x) + 1.0f); }

__device__ __forceinline__ u64 dupf(float x) {
    unsigned b = __float_as_uint(x);
    return ((u64)b << 32) | (u64)b;
}
__device__ __forceinline__ void ffma2(u64& d, u64 a, u64 b) {
    asm("fma.rn.f32x2 %0, %1, %2, %3;" : "=l"(d) : "l"(a), "l"(b), "l"(d));
}
__device__ __forceinline__ u64 addf2(u64 a, u64 b) {
    u64 r; asm("add.rn.f32x2 %0, %1, %2;" : "=l"(r) : "l"(a), "l"(b)); return r;
}

__global__ void bias_prep(const float* __restrict__ b_ioux, const float* __restrict__ b_iouh,
                          const float* __restrict__ b_fx, const float* __restrict__ b_fh) {
    int j = threadIdx.x + blockIdx.x * blockDim.x;
    if (j < IOU)        g_bias[j] = b_ioux[j] + b_iouh[j];
    else if (j < XCOLS) g_bias[j] = b_fx[j - IOU] + b_fh[j - IOU];
}

// ---------------------------------------------------------------------------
// Tiled SGEMM with packed fma.rn.f32x2 inner loop.
// MODE 0: A = inputs (lda=IN_DIM); cols<768 -> W0(W_ioux), else W1(W_fx); C=g_P (+bias)
// MODE 1: A gathered from h by column region:
//         [0,768): hsum=h[2n+1]+h[2n+2], W_iouh | [768,1024): h[2n+1], W_fh |
//         [1024,1280): h[2n+2], W_fh ; C = g_G
// ---------------------------------------------------------------------------
#define BM 128
#define BN 128
#define BK 16
#define TM 8
#define TN 8

template<int MODE>
__global__ __launch_bounds__(256, 2)
void gemm_kernel(int M, int K, int colOff,
                 const float* __restrict__ A, int lda,
                 const float* __restrict__ hbase, int level_start,
                 const float* __restrict__ W0, const float* __restrict__ W1)
{
    __shared__ u64   As2[BK][BM];   // duplicated pairs {a,a} -> broadcast operand
    __shared__ float Bs[BK][BN];

    const int tid = threadIdx.x;
    const int tx = tid & 15;
    const int ty = tid >> 4;
    const int m0 = blockIdx.y * BM;
    const int colBase = colOff + blockIdx.x * BN;

    float* Cbase = (MODE == 0) ? g_P : g_G;
    const int ldc = (MODE == 0) ? XCOLS : GCOLS;

    const float* Wsrc;
    int wrow0;
    int region = 0;
    if (MODE == 0) {
        if (colBase < IOU) { Wsrc = W0; wrow0 = colBase; }
        else               { Wsrc = W1; wrow0 = colBase - IOU; }
    } else {
        if (colBase < IOU)            { Wsrc = W0; wrow0 = colBase;             region = 0; }
        else if (colBase < IOU + MEM) { Wsrc = W1; wrow0 = colBase - IOU;       region = 1; }
        else                          { Wsrc = W1; wrow0 = colBase - IOU - MEM; region = 2; }
    }

    u64 acc2[TM][TN / 2];
    #pragma unroll
    for (int i = 0; i < TM; i++)
        #pragma unroll
        for (int p = 0; p < TN / 2; p++) acc2[i][p] = 0ULL;

    const int nIter = (K + BK - 1) / BK;
    for (int it = 0; it < nIter; it++) {
        const int k0 = it * BK;

        // ---- load A tile (transposed, duplicated pairs into As2[k][m]) ----
        #pragma unroll
        for (int ld = 0; ld < 2; ld++) {
            int e   = tid * 2 + ld;          // 0..511
            int row = e >> 2;                // 0..127
            int kq  = (e & 3) << 2;          // 0,4,8,12
            int k   = k0 + kq;
            float4 av = make_float4(0.f, 0.f, 0.f, 0.f);
            int gm = m0 + row;
            if (gm < M) {
                if (MODE == 0) {
                    if (k + 3 < K) {
                        av = *reinterpret_cast<const float4*>(A + (size_t)gm * lda + k);
                    } else {
                        float t[4] = {0.f, 0.f, 0.f, 0.f};
                        #pragma unroll
                        for (int q = 0; q < 4; q++)
                            if (k + q < K) t[q] = A[(size_t)gm * lda + k + q];
                        av = make_float4(t[0], t[1], t[2], t[3]);
                    }
                } else {
                    size_t node = (size_t)level_start + gm;
                    if (region != 2) {
                        av = *reinterpret_cast<const float4*>(hbase + (2 * node + 1) * MEM + k);
                    }
                    if (region != 1) {
                        float4 r4 = *reinterpret_cast<const float4*>(hbase + (2 * node + 2) * MEM + k);
                        if (region == 0) { av.x += r4.x; av.y += r4.y; av.z += r4.z; av.w += r4.w; }
                        else             { av = r4; }
                    }
                }
            }
            As2[kq + 0][row] = dupf(av.x);
            As2[kq + 1][row] = dupf(av.y);
            As2[kq + 2][row] = dupf(av.z);
            As2[kq + 3][row] = dupf(av.w);
        }

        // ---- load B tile (W rows, transposed into Bs[k][n]) ----
        #pragma unroll
        for (int ld = 0; ld < 2; ld++) {
            int e   = tid * 2 + ld;
            int row = e >> 2;
            int kq  = (e & 3) << 2;
            int k   = k0 + kq;
            float4 bv = make_float4(0.f, 0.f, 0.f, 0.f);
            const float* src = Wsrc + (size_t)(wrow0 + row) * K + k;
            if (k + 3 < K) {
                bv = *reinterpret_cast<const float4*>(src);
            } else {
                float t[4] = {0.f, 0.f, 0.f, 0.f};
                #pragma unroll
                for (int q = 0; q < 4; q++)
                    if (k + q < K) t[q] = src[q];
                bv = make_float4(t[0], t[1], t[2], t[3]);
            }
            Bs[kq + 0][row] = bv.x;
            Bs[kq + 1][row] = bv.y;
            Bs[kq + 2][row] = bv.z;
            Bs[kq + 3][row] = bv.w;
        }

        __syncthreads();

        #pragma unroll
        for (int kk = 0; kk < BK; kk++) {
            ulonglong2 a01 = *reinterpret_cast<const ulonglong2*>(&As2[kk][ty * TM + 0]);
            ulonglong2 a23 = *reinterpret_cast<const ulonglong2*>(&As2[kk][ty * TM + 2]);
            ulonglong2 a45 = *reinterpret_cast<const ulonglong2*>(&As2[kk][ty * TM + 4]);
            ulonglong2 a67 = *reinterpret_cast<const ulonglong2*>(&As2[kk][ty * TM + 6]);
            ulonglong2 bp0 = *reinterpret_cast<const ulonglong2*>(&Bs[kk][tx * TN + 0]);
            ulonglong2 bp1 = *reinterpret_cast<const ulonglong2*>(&Bs[kk][tx * TN + 4]);
            u64 a2[TM] = {a01.x, a01.y, a23.x, a23.y, a45.x, a45.y, a67.x, a67.y};
            u64 b2[TN / 2] = {bp0.x, bp0.y, bp1.x, bp1.y};
            #pragma unroll
            for (int i = 0; i < TM; i++)
                #pragma unroll
                for (int p = 0; p < TN / 2; p++)
                    ffma2(acc2[i][p], a2[i], b2[p]);
        }

        __syncthreads();
    }

    // ---- epilogue ----
    u64 bias2[TN / 2];
    if (MODE == 0) {
        #pragma unroll
        for (int p = 0; p < TN / 2; p++)
            bias2[p] = *reinterpret_cast<const u64*>(&g_bias[colBase + tx * TN + 2 * p]);
    }
    #pragma unroll
    for (int i = 0; i < TM; i++) {
        int gm = m0 + ty * TM + i;
        if (gm >= M) continue;
        float* crow = Cbase + (size_t)gm * ldc + colBase + tx * TN;
        ulonglong2 v0, v1;
        if (MODE == 0) {
            v0.x = addf2(acc2[i][0], bias2[0]);
            v0.y = addf2(acc2[i][1], bias2[1]);
            v1.x = addf2(acc2[i][2], bias2[2]);
            v1.y = addf2(acc2[i][3], bias2[3]);
        } else {
            v0.x = acc2[i][0]; v0.y = acc2[i][1];
            v1.x = acc2[i][2]; v1.y = acc2[i][3];
        }
        *reinterpret_cast<ulonglong2*>(crow + 0) = v0;
        *reinterpret_cast<ulonglong2*>(crow + 4) = v1;
    }
}

// Leaves (level 15): c = sig(i)*tanh(u), h = sig(o)*tanh(c). Vectorized float4.
__global__ void leaf_kernel(float* __restrict__ c_out, float* __restrict__ h_out) {
    int t = blockIdx.x * blockDim.x + threadIdx.x;     // NLEAF*64 threads
    int node = LEAF_START + (t >> 6);
    int m = (t & 63) * 4;
    const float* p = g_P + (size_t)node * XCOLS;
    float4 iv = *reinterpret_cast<const float4*>(p + m);
    float4 ov = *reinterpret_cast<const float4*>(p + MEM + m);
    float4 uv = *reinterpret_cast<const float4*>(p + 2 * MEM + m);
    float4 cn, hn;
    cn.x = sigmoidf_(iv.x) * tanhf_(uv.x);  hn.x = sigmoidf_(ov.x) * tanhf_(cn.x);
    cn.y = sigmoidf_(iv.y) * tanhf_(uv.y);  hn.y = sigmoidf_(ov.y) * tanhf_(cn.y);
    cn.z = sigmoidf_(iv.z) * tanhf_(uv.z);  hn.z = sigmoidf_(ov.z) * tanhf_(cn.z);
    cn.w = sigmoidf_(iv.w) * tanhf_(uv.w);  hn.w = sigmoidf_(ov.w) * tanhf_(cn.w);
    *reinterpret_cast<float4*>(c_out + (size_t)node * MEM + m) = cn;
    *reinterpret_cast<float4*>(h_out + (size_t)node * MEM + m) = hn;
}

// Internal-node combine for one level. Vectorized float4.
__global__ void combine_kernel(int start, int size, float* __restrict__ c_out, float* __restrict__ h_out) {
    int t = blockIdx.x * blockDim.x + threadIdx.x;     // size*64 threads
    int r = t >> 6;
    if (r >= size) return;
    int node = start + r;
    int m = (t & 63) * 4;
    const float* p = g_P + (size_t)node * XCOLS;
    const float* g = g_G + (size_t)r * GCOLS;
    float4 pi = *reinterpret_cast<const float4*>(p + m);
    float4 po = *reinterpret_cast<const float4*>(p + MEM + m);
    float4 pu = *reinterpret_cast<const float4*>(p + 2 * MEM + m);
    float4 fx = *reinterpret_cast<const float4*>(p + IOU + m);
    float4 gi = *reinterpret_cast<const float4*>(g + m);
    float4 go = *reinterpret_cast<const float4*>(g + MEM + m);
    float4 gu = *reinterpret_cast<const float4*>(g + 2 * MEM + m);
    float4 gl = *reinterpret_cast<const float4*>(g + IOU + m);
    float4 gr = *reinterpret_cast<const float4*>(g + IOU + MEM + m);
    float4 cl = *reinterpret_cast<const float4*>(c_out + (size_t)(2 * node + 1) * MEM + m);
    float4 cr = *reinterpret_cast<const float4*>(c_out + (size_t)(2 * node + 2) * MEM + m);
    float4 cn, hn;
    #define COMB(f) { \
        float fl = sigmoidf_(fx.f + gl.f); \
        float fr = sigmoidf_(fx.f + gr.f); \
        cn.f = sigmoidf_(pi.f + gi.f) * tanhf_(pu.f + gu.f) + fl * cl.f + fr * cr.f; \
        hn.f = sigmoidf_(po.f + go.f) * tanhf_(cn.f); }
    COMB(x) COMB(y) COMB(z) COMB(w)
    #undef COMB
    *reinterpret_cast<float4*>(c_out + (size_t)node * MEM + m) = cn;
    *reinterpret_cast<float4*>(h_out + (size_t)node * MEM + m) = hn;
}

extern "C" void kernel_launch(void* const* d_in, const int* in_sizes, int n_in,
                              void* d_out, int out_size) {
    const float* inputs = (const float*)d_in[0];
    const float* W_ioux = (const float*)d_in[1];
    const float* b_ioux = (const float*)d_in[2];
    const float* W_iouh = (const float*)d_in[3];
    const float* b_iouh = (const float*)d_in[4];
    const float* W_fx   = (const float*)d_in[5];
    const float* b_fx   = (const float*)d_in[6];
    const float* W_fh   = (const float*)d_in[7];
    const float* b_fh   = (const float*)d_in[8];

    float* c_out = (float*)d_out;                          // [N, 256]
    float* h_out = c_out + (size_t)NNODES * MEM;           // [N, 256]

    bias_prep<<<4, 256>>>(b_ioux, b_iouh, b_fx, b_fh);

    // x-projection: iou columns for ALL nodes
    {
        dim3 grid(IOU / BN, (NNODES + BM - 1) / BM);       // (6, 512)
        gemm_kernel<0><<<grid, 256>>>(NNODES, IN_DIM, 0,
                                      inputs, IN_DIM, nullptr, 0, W_ioux, W_fx);
    }
    // x-projection: fx columns only for internal nodes (leaves never read them)
    {
        dim3 grid(MEM / BN, (NINTERNAL + BM - 1) / BM);    // (2, 256)
        gemm_kernel<0><<<grid, 256>>>(NINTERNAL, IN_DIM, IOU,
                                      inputs, IN_DIM, nullptr, 0, W_ioux, W_fx);
    }

    // Leaves
    leaf_kernel<<<NLEAF * 64 / 256, 256>>>(c_out, h_out);

    // Levels 14..0 (children always computed before parents)
    for (int d = 14; d >= 0; d--) {
        int size = 1 << d;
        int start = size - 1;
        dim3 grid(GCOLS / BN, (size + BM - 1) / BM);       // (10, ceil(size/128))
        gemm_kernel<1><<<grid, 256>>>(size, MEM, 0,
                                      nullptr, 0, h_out, start, W_iouh, W_fh);
        int cthreads = size * 64;
        combine_kernel<<<(cthreads + 255) / 256, 256>>>(start, size, c_out, h_out);
    }
}

// round 8
// speedup vs baseline: 2.2345x; 2.2345x over previous
#include <cuda_runtime.h>
#include <cuda_bf16.h>
#include <math.h>
#include <stdint.h>

#define NNODES 65535
#define IN_DIM 300
#define KXPAD 320          // IN_DIM padded to 5 chunks of 64
#define MEM 256
#define IOU 768
#define XCOLS 1024         // 768 iou + 256 fx
#define GCOLS 1280         // 768 iou-rec + 256 f_l + 256 f_r
#define KREC 512           // [h_left | h_right]
#define NINTERNAL 32767
#define LEAF_START 32767
#define NLEAF 32768

// ---------------- scratch (__device__ globals; no allocs allowed) ----------
__device__ float g_P[(size_t)NNODES * XCOLS];       // x-projections (+bias)
__device__ float g_G[(size_t)16384 * GCOLS];        // per-level recurrent GEMM
__device__ float g_bias[XCOLS];
__device__ __nv_bfloat16 g_Xhi[(size_t)NNODES * KXPAD];
__device__ __nv_bfloat16 g_Xlo[(size_t)NNODES * KXPAD];
__device__ __nv_bfloat16 g_WXhi[(size_t)XCOLS * KXPAD];   // [W_ioux ; W_fx] padded
__device__ __nv_bfloat16 g_WXlo[(size_t)XCOLS * KXPAD];
__device__ __nv_bfloat16 g_WRhi[(size_t)GCOLS * KREC];    // concat recurrent W
__device__ __nv_bfloat16 g_WRlo[(size_t)GCOLS * KREC];
__device__ __nv_bfloat16 g_Hhi[(size_t)NNODES * MEM];
__device__ __nv_bfloat16 g_Hlo[(size_t)NNODES * MEM];

__device__ __forceinline__ float sigmoidf_(float x) { return 1.0f / (1.0f + __expf(-x)); }
__device__ __forceinline__ float tanhf_(float x)    { return 1.0f - 2.0f / (__expf(2.0f * x) + 1.0f); }

__device__ __forceinline__ void split2(float x, __nv_bfloat16& hi, __nv_bfloat16& lo) {
    hi = __float2bfloat16(x);
    lo = __float2bfloat16(x - __bfloat162float(hi));
}

static __device__ __forceinline__ uint32_t s2u(const void* p) {
    return (uint32_t)__cvta_generic_to_shared(p);
}

// ---------------- warp-MMA primitives (sm_80+ PTX, valid on sm_103) --------
__device__ __forceinline__ void ldm4(uint32_t* r, uint32_t addr) {
    asm volatile("ldmatrix.sync.aligned.m8n8.x4.shared.b16 {%0,%1,%2,%3}, [%4];"
                 : "=r"(r[0]), "=r"(r[1]), "=r"(r[2]), "=r"(r[3]) : "r"(addr));
}
__device__ __forceinline__ void mma16816(float* d, const uint32_t* a, const uint32_t* b) {
    asm volatile("mma.sync.aligned.m16n8k16.row.col.f32.bf16.bf16.f32 "
                 "{%0,%1,%2,%3},{%4,%5,%6,%7},{%8,%9},{%0,%1,%2,%3};"
                 : "+f"(d[0]), "+f"(d[1]), "+f"(d[2]), "+f"(d[3])
                 : "r"(a[0]), "r"(a[1]), "r"(a[2]), "r"(a[3]), "r"(b[0]), "r"(b[1]));
}
__device__ __forceinline__ void cp16(uint32_t dst, const void* src, int srcBytes) {
    asm volatile("cp.async.cg.shared.global [%0], [%1], 16, %2;"
                 :: "r"(dst), "l"(src), "r"(srcBytes) : "memory");
}
__device__ __forceinline__ void cp_commit() { asm volatile("cp.async.commit_group;" ::: "memory"); }
__device__ __forceinline__ void cp_wait1()  { asm volatile("cp.async.wait_group 1;" ::: "memory"); }
__device__ __forceinline__ void cp_wait0()  { asm volatile("cp.async.wait_group 0;" ::: "memory"); }

// ---------------- prep kernels ----------------------------------------------
__global__ void bias_prep(const float* __restrict__ b_ioux, const float* __restrict__ b_iouh,
                          const float* __restrict__ b_fx, const float* __restrict__ b_fh) {
    int j = threadIdx.x + blockIdx.x * blockDim.x;
    if (j < IOU)        g_bias[j] = b_ioux[j] + b_iouh[j];
    else if (j < XCOLS) g_bias[j] = b_fx[j - IOU] + b_fh[j - IOU];
}

__global__ void split_x(const float* __restrict__ inputs) {
    size_t t = (size_t)blockIdx.x * blockDim.x + threadIdx.x;
    if (t >= (size_t)NNODES * KXPAD) return;
    int row = (int)(t / KXPAD);
    int col = (int)(t % KXPAD);
    float v = (col < IN_DIM) ? inputs[(size_t)row * IN_DIM + col] : 0.0f;
    split2(v, g_Xhi[t], g_Xlo[t]);
}

__global__ void build_wx(const float* __restrict__ W_ioux, const float* __restrict__ W_fx) {
    size_t t = (size_t)blockIdx.x * blockDim.x + threadIdx.x;
    if (t >= (size_t)XCOLS * KXPAD) return;
    int r = (int)(t / KXPAD);
    int k = (int)(t % KXPAD);
    float v = 0.0f;
    if (k < IN_DIM) v = (r < IOU) ? W_ioux[(size_t)r * IN_DIM + k]
                                  : W_fx[(size_t)(r - IOU) * IN_DIM + k];
    split2(v, g_WXhi[t], g_WXlo[t]);
}

__global__ void build_wr(const float* __restrict__ W_iouh, const float* __restrict__ W_fh) {
    size_t t = (size_t)blockIdx.x * blockDim.x + threadIdx.x;
    if (t >= (size_t)GCOLS * KREC) return;
    int r = (int)(t / KREC);
    int k = (int)(t % KREC);
    int kk = (k < MEM) ? k : k - MEM;
    float v = 0.0f;
    if (r < IOU)                 v = W_iouh[(size_t)r * MEM + kk];          // both halves
    else if (r < IOU + MEM) { if (k < MEM)  v = W_fh[(size_t)(r - IOU) * MEM + kk]; }
    else                    { if (k >= MEM) v = W_fh[(size_t)(r - IOU - MEM) * MEM + kk]; }
    split2(v, g_WRhi[t], g_WRlo[t]);
}

// ---------------- tensor-core GEMM (mma.sync, bf16x3) -----------------------
// MODE 0: C=g_P (+bias). A=g_Xhi/lo [NNODES x 320], B=g_WXhi/lo [1024 x 320].
// MODE 1: C=g_G. A = gathered child h (K=512: k<256 left child, else right),
//         B=g_WRhi/lo [1280 x 512].
// Block 128x128, 8 warps (2m x 4n), warp tile 64x32, K-chunk 64, double-buffered.
#define S_AHI 0
#define S_ALO 16384
#define S_BHI 32768
#define S_BLO 49152
#define BUF_STRIDE 65536
#define SMEM_DYN (1024 + 2 * BUF_STRIDE)

template<int MODE>
__global__ __launch_bounds__(256)
void mma_gemm(int M, int colOff, int level_start)
{
    extern __shared__ char dsm[];
    const int tid = threadIdx.x;
    const uint32_t raw = s2u(dsm);
    const uint32_t sbase = (raw + 1023u) & ~1023u;

    const int m0 = blockIdx.y * 128;
    const int colBase = colOff + blockIdx.x * 128;
    const int KW  = (MODE == 0) ? KXPAD : KREC;
    const int NCH = KW / 64;

    const __nv_bfloat16* Ahi = (MODE == 0) ? g_Xhi : g_Hhi;
    const __nv_bfloat16* Alo = (MODE == 0) ? g_Xlo : g_Hlo;
    const __nv_bfloat16* Bhi = (MODE == 0) ? g_WXhi : g_WRhi;
    const __nv_bfloat16* Blo = (MODE == 0) ? g_WXlo : g_WRlo;

    const int wid  = tid >> 5;
    const int lane = tid & 31;
    const int wm = (wid >> 2) * 64;       // warp m-origin within block
    const int wn = (wid & 3) * 32;        // warp n-origin within block

    float acc[4][4][4];
    #pragma unroll
    for (int mt = 0; mt < 4; mt++)
        #pragma unroll
        for (int nt = 0; nt < 4; nt++)
            #pragma unroll
            for (int q = 0; q < 4; q++) acc[mt][nt][q] = 0.0f;

    // ---- async load of one K-chunk into buffer `buf`
    auto issue_chunk = [&](int ch, int buf) {
        const int k0 = ch * 64;
        const uint32_t db = sbase + buf * BUF_STRIDE;
        #pragma unroll
        for (int i = 0; i < 4; i++) {
            int u   = tid + i * 256;          // 16B unit 0..1023
            int row = u >> 3;
            int cb  = (u & 7) * 16;           // byte within 128B row
            int off = row * 128 + cb;
            int sw  = off ^ ((off >> 3) & 0x70);
            // A (predicated zfill for OOB rows)
            int gm = m0 + row;
            int pbytes = (gm < M) ? 16 : 0;
            size_t eoff;
            if (MODE == 0) {
                eoff = (size_t)(gm < M ? gm : 0) * KXPAD + k0 + (cb >> 1);
            } else {
                int k = k0 + (cb >> 1);       // 0..511 (chunk never straddles 256)
                size_t node = (size_t)level_start + (gm < M ? gm : 0);
                size_t child = (k < MEM) ? (2 * node + 1) : (2 * node + 2);
                eoff = child * MEM + (k & (MEM - 1));
            }
            cp16(db + S_AHI + sw, Ahi + eoff, pbytes);
            cp16(db + S_ALO + sw, Alo + eoff, pbytes);
            // B (always in range: grids cover exact column counts)
            size_t beoff = (size_t)(colBase + row) * KW + k0 + (cb >> 1);
            cp16(db + S_BHI + sw, Bhi + beoff, 16);
            cp16(db + S_BLO + sw, Blo + beoff, 16);
        }
    };

    issue_chunk(0, 0);
    cp_commit();

    for (int ch = 0; ch < NCH; ch++) {
        if (ch + 1 < NCH) {
            issue_chunk(ch + 1, (ch + 1) & 1);
            cp_commit();
            cp_wait1();
        } else {
            cp_wait0();
        }
        __syncthreads();

        const uint32_t db = sbase + (ch & 1) * BUF_STRIDE;
        #pragma unroll
        for (int ks = 0; ks < 4; ks++) {
            // A fragments (4 m-tiles, hi+lo)
            uint32_t ah[4][4], al[4][4];
            #pragma unroll
            for (int mt = 0; mt < 4; mt++) {
                int row = wm + mt * 16 + (lane & 15);
                int col = ks * 16 + (lane >> 4) * 8;
                int off = row * 128 + col * 2;
                int sw  = off ^ ((off >> 3) & 0x70);
                ldm4(ah[mt], db + S_AHI + sw);
                ldm4(al[mt], db + S_ALO + sw);
            }
            // B fragments (2 n-tile pairs covering n32, hi+lo)
            uint32_t bh[2][4], bl[2][4];
            #pragma unroll
            for (int bp = 0; bp < 2; bp++) {
                int n = wn + bp * 16 + ((lane >> 4) << 3) + (lane & 7);
                int k = ks * 16 + ((lane >> 3) & 1) * 8;
                int off = n * 128 + k * 2;
                int sw  = off ^ ((off >> 3) & 0x70);
                ldm4(bh[bp], db + S_BHI + sw);
                ldm4(bl[bp], db + S_BLO + sw);
            }
            // 3-pass bf16x3 MMAs
            #pragma unroll
            for (int mt = 0; mt < 4; mt++)
                #pragma unroll
                for (int nt = 0; nt < 4; nt++) {
                    const uint32_t* bhp = &bh[nt >> 1][(nt & 1) * 2];
                    const uint32_t* blp = &bl[nt >> 1][(nt & 1) * 2];
                    mma16816(acc[mt][nt], ah[mt], bhp);
                    mma16816(acc[mt][nt], ah[mt], blp);
                    mma16816(acc[mt][nt], al[mt], bhp);
                }
        }
        __syncthreads();
    }

    // ---- epilogue: fp32 frag -> global C (+bias for MODE 0)
    float* Cbase = (MODE == 0) ? g_P : g_G;
    const int ldc = (MODE == 0) ? XCOLS : GCOLS;
    #pragma unroll
    for (int mt = 0; mt < 4; mt++) {
        #pragma unroll
        for (int h = 0; h < 2; h++) {
            int grow = m0 + wm + mt * 16 + (lane >> 2) + h * 8;
            if (grow >= M) continue;
            float* crow = Cbase + (size_t)grow * ldc + colBase + wn;
            #pragma unroll
            for (int nt = 0; nt < 4; nt++) {
                int col = nt * 8 + (lane & 3) * 2;
                float2 v;
                v.x = acc[mt][nt][h * 2 + 0];
                v.y = acc[mt][nt][h * 2 + 1];
                if (MODE == 0) {
                    float2 b2 = *reinterpret_cast<const float2*>(g_bias + colBase + wn + col);
                    v.x += b2.x; v.y += b2.y;
                }
                *reinterpret_cast<float2*>(crow + col) = v;
            }
        }
    }
}

// ---------------- elementwise ------------------------------------------------
__global__ void leaf_kernel(float* __restrict__ c_out, float* __restrict__ h_out) {
    int t = blockIdx.x * blockDim.x + threadIdx.x;     // NLEAF*64 threads
    int node = LEAF_START + (t >> 6);
    int m = (t & 63) * 4;
    const float* p = g_P + (size_t)node * XCOLS;
    float4 iv = *reinterpret_cast<const float4*>(p + m);
    float4 ov = *reinterpret_cast<const float4*>(p + MEM + m);
    float4 uv = *reinterpret_cast<const float4*>(p + 2 * MEM + m);
    float4 cn, hn;
    cn.x = sigmoidf_(iv.x) * tanhf_(uv.x);  hn.x = sigmoidf_(ov.x) * tanhf_(cn.x);
    cn.y = sigmoidf_(iv.y) * tanhf_(uv.y);  hn.y = sigmoidf_(ov.y) * tanhf_(cn.y);
    cn.z = sigmoidf_(iv.z) * tanhf_(uv.z);  hn.z = sigmoidf_(ov.z) * tanhf_(cn.z);
    cn.w = sigmoidf_(iv.w) * tanhf_(uv.w);  hn.w = sigmoidf_(ov.w) * tanhf_(cn.w);
    size_t o = (size_t)node * MEM + m;
    *reinterpret_cast<float4*>(c_out + o) = cn;
    *reinterpret_cast<float4*>(h_out + o) = hn;
    __nv_bfloat16 hi[4], lo[4];
    split2(hn.x, hi[0], lo[0]); split2(hn.y, hi[1], lo[1]);
    split2(hn.z, hi[2], lo[2]); split2(hn.w, hi[3], lo[3]);
    *reinterpret_cast<uint2*>(g_Hhi + o) = *reinterpret_cast<uint2*>(hi);
    *reinterpret_cast<uint2*>(g_Hlo + o) = *reinterpret_cast<uint2*>(lo);
}

__global__ void combine_kernel(int start, int size, float* __restrict__ c_out, float* __restrict__ h_out) {
    int t = blockIdx.x * blockDim.x + threadIdx.x;     // size*64 threads
    int r = t >> 6;
    if (r >= size) return;
    int node = start + r;
    int m = (t & 63) * 4;
    const float* p = g_P + (size_t)node * XCOLS;
    const float* g = g_G + (size_t)r * GCOLS;
    float4 pi = *reinterpret_cast<const float4*>(p + m);
    float4 po = *reinterpret_cast<const float4*>(p + MEM + m);
    float4 pu = *reinterpret_cast<const float4*>(p + 2 * MEM + m);
    float4 fx = *reinterpret_cast<const float4*>(p + IOU + m);
    float4 gi = *reinterpret_cast<const float4*>(g + m);
    float4 go = *reinterpret_cast<const float4*>(g + MEM + m);
    float4 gu = *reinterpret_cast<const float4*>(g + 2 * MEM + m);
    float4 gl = *reinterpret_cast<const float4*>(g + IOU + m);
    float4 gr = *reinterpret_cast<const float4*>(g + IOU + MEM + m);
    float4 cl = *reinterpret_cast<const float4*>(c_out + (size_t)(2 * node + 1) * MEM + m);
    float4 cr = *reinterpret_cast<const float4*>(c_out + (size_t)(2 * node + 2) * MEM + m);
    float4 cn, hn;
    #define COMB(f) { \
        float fl = sigmoidf_(fx.f + gl.f); \
        float fr = sigmoidf_(fx.f + gr.f); \
        cn.f = sigmoidf_(pi.f + gi.f) * tanhf_(pu.f + gu.f) + fl * cl.f + fr * cr.f; \
        hn.f = sigmoidf_(po.f + go.f) * tanhf_(cn.f); }
    COMB(x) COMB(y) COMB(z) COMB(w)
    #undef COMB
    size_t o = (size_t)node * MEM + m;
    *reinterpret_cast<float4*>(c_out + o) = cn;
    *reinterpret_cast<float4*>(h_out + o) = hn;
    __nv_bfloat16 hi[4], lo[4];
    split2(hn.x, hi[0], lo[0]); split2(hn.y, hi[1], lo[1]);
    split2(hn.z, hi[2], lo[2]); split2(hn.w, hi[3], lo[3]);
    *reinterpret_cast<uint2*>(g_Hhi + o) = *reinterpret_cast<uint2*>(hi);
    *reinterpret_cast<uint2*>(g_Hlo + o) = *reinterpret_cast<uint2*>(lo);
}

// ---------------- launch ------------------------------------------------------
extern "C" void kernel_launch(void* const* d_in, const int* in_sizes, int n_in,
                              void* d_out, int out_size) {
    const float* inputs = (const float*)d_in[0];
    const float* W_ioux = (const float*)d_in[1];
    const float* b_ioux = (const float*)d_in[2];
    const float* W_iouh = (const float*)d_in[3];
    const float* b_iouh = (const float*)d_in[4];
    const float* W_fx   = (const float*)d_in[5];
    const float* b_fx   = (const float*)d_in[6];
    const float* W_fh   = (const float*)d_in[7];
    const float* b_fh   = (const float*)d_in[8];

    float* c_out = (float*)d_out;                      // [N, 256]
    float* h_out = c_out + (size_t)NNODES * MEM;       // [N, 256]

    cudaFuncSetAttribute(mma_gemm<0>, cudaFuncAttributeMaxDynamicSharedMemorySize, SMEM_DYN);
    cudaFuncSetAttribute(mma_gemm<1>, cudaFuncAttributeMaxDynamicSharedMemorySize, SMEM_DYN);

    bias_prep<<<4, 256>>>(b_ioux, b_iouh, b_fx, b_fh);
    {
        size_t tot = (size_t)NNODES * KXPAD;
        split_x<<<(unsigned)((tot + 255) / 256), 256>>>(inputs);
    }
    {
        size_t tot = (size_t)XCOLS * KXPAD;
        build_wx<<<(unsigned)((tot + 255) / 256), 256>>>(W_ioux, W_fx);
    }
    {
        size_t tot = (size_t)GCOLS * KREC;
        build_wr<<<(unsigned)((tot + 255) / 256), 256>>>(W_iouh, W_fh);
    }

    // x-projection: iou columns for ALL nodes
    {
        dim3 grid(6, (NNODES + 127) / 128);            // 6 x 512
        mma_gemm<0><<<grid, 256, SMEM_DYN>>>(NNODES, 0, 0);
    }
    // fx columns only for internal nodes
    {
        dim3 grid(2, (NINTERNAL + 127) / 128);         // 2 x 256
        mma_gemm<0><<<grid, 256, SMEM_DYN>>>(NINTERNAL, IOU, 0);
    }

    leaf_kernel<<<NLEAF * 64 / 256, 256>>>(c_out, h_out);

    for (int d = 14; d >= 0; d--) {
        int size = 1 << d;
        int start = size - 1;
        dim3 grid(10, (size + 127) / 128);
        mma_gemm<1><<<grid, 256, SMEM_DYN>>>(size, 0, start);
        int cthreads = size * 64;
        combine_kernel<<<(cthreads + 255) / 256, 256>>>(start, size, c_out, h_out);
    }
}